// round 4
// baseline (speedup 1.0000x reference)
#include <cuda_runtime.h>
#include <cuda_bf16.h>

// Problem constants
#define GRID_N   256
#define NB       1024
#define NH       32
#define NL       8
#define NS       8
#define BOUNDS_LO (-1.28f)
#define GRID_RES  (0.01f)
#define DIST_THR  (-0.01f)

// 1 thread per (b,h,l); 8 independent gathers per thread (MLP=8).
// Pose data staged through shared via coalesced float4 loads.
// 7 blocks/SM resident -> 1024-block grid runs in a single wave.
__global__ __launch_bounds__(256, 7)
void voxel_collision_kernel(const float* __restrict__ link_pos,   // [B,H,L,3]
                            const float* __restrict__ link_rot,   // [B,H,L,3,3]
                            const float* __restrict__ sph_ctr,    // [L,S,3]
                            const float* __restrict__ sph_rad,    // [L,S]
                            const float* __restrict__ sdf,        // [256^3]
                            const float* __restrict__ weight,     // scalar
                            float* __restrict__ out)              // [B,H]
{
    // Block covers 256 (b,h,l) units.
    __shared__ float s_rot[256 * 9];       // 2304 floats
    __shared__ float s_pos[256 * 3];       // 768 floats
    __shared__ float s_ctr[NL * NS * 3];   // 192 floats
    __shared__ float s_rad[NL * NS];       // 64 floats

    // Coalesced float4 staging of this block's pose data.
    {
        const float4* g4 = (const float4*)(link_rot + (size_t)blockIdx.x * 2304);
        float4* s4 = (float4*)s_rot;
        #pragma unroll
        for (int i = threadIdx.x; i < 576; i += 256) s4[i] = __ldg(&g4[i]);

        const float4* p4 = (const float4*)(link_pos + (size_t)blockIdx.x * 768);
        float4* sp4 = (float4*)s_pos;
        if (threadIdx.x < 192) sp4[threadIdx.x] = __ldg(&p4[threadIdx.x]);

        if (threadIdx.x < NL * NS * 3) s_ctr[threadIdx.x] = sph_ctr[threadIdx.x];
        if (threadIdx.x < NL * NS)     s_rad[threadIdx.x] = sph_rad[threadIdx.x];
    }
    __syncthreads();

    const int u = threadIdx.x;               // local (b,h,l) unit
    const int l = u & (NL - 1);              // link id (block is 8-aligned)

    const float r00 = s_rot[u * 9 + 0], r01 = s_rot[u * 9 + 1], r02 = s_rot[u * 9 + 2];
    const float r10 = s_rot[u * 9 + 3], r11 = s_rot[u * 9 + 4], r12 = s_rot[u * 9 + 5];
    const float r20 = s_rot[u * 9 + 6], r21 = s_rot[u * 9 + 7], r22 = s_rot[u * 9 + 8];
    const float px = s_pos[u * 3 + 0], py = s_pos[u * 3 + 1], pz = s_pos[u * 3 + 2];

    // 8 gather offsets computed back-to-back, then 8 independent loads.
    int off[NS];
    #pragma unroll
    for (int s = 0; s < NS; s++) {
        const float* c = &s_ctr[(l * NS + s) * 3];
        const float cx = c[0], cy = c[1], cz = c[2];
        // mul-then-add, round-to-nearest, no FMA contraction (identical to
        // the passing rounds' numerics; rel_err 1.95e-4).
        float x = __fadd_rn(__fadd_rn(__fadd_rn(__fmul_rn(r00, cx), __fmul_rn(r01, cy)), __fmul_rn(r02, cz)), px);
        float y = __fadd_rn(__fadd_rn(__fadd_rn(__fmul_rn(r10, cx), __fmul_rn(r11, cy)), __fmul_rn(r12, cz)), py);
        float z = __fadd_rn(__fadd_rn(__fadd_rn(__fmul_rn(r20, cx), __fmul_rn(r21, cy)), __fmul_rn(r22, cz)), pz);

        int ix = (int)floorf(__fdiv_rn(__fsub_rn(x, BOUNDS_LO), GRID_RES));
        int iy = (int)floorf(__fdiv_rn(__fsub_rn(y, BOUNDS_LO), GRID_RES));
        int iz = (int)floorf(__fdiv_rn(__fsub_rn(z, BOUNDS_LO), GRID_RES));
        ix = min(max(ix, 0), GRID_N - 1);
        iy = min(max(iy, 0), GRID_N - 1);
        iz = min(max(iz, 0), GRID_N - 1);
        off[s] = ((ix * GRID_N) + iy) * GRID_N + iz;
    }

    float sval[NS];
    #pragma unroll
    for (int s = 0; s < NS; s++)
        sval[s] = __ldg(&sdf[off[s]]);

    const float w = __ldg(weight);           // off the critical path

    // per-link worst penetration
    float m = -1e30f;
    #pragma unroll
    for (int s = 0; s < NS; s++)
        m = fmaxf(m, s_rad[l * NS + s] - sval[s]);

    // threshold / clamp / normalize:  clip(m - 0.01, 0, 0.5) / 0.25
    float res = m + DIST_THR;
    res = fminf(fmaxf(res, 0.0f), 0.5f) * 4.0f;

    // sum the 8 links of each (b,h): lanes [8k..8k+7] reduce to lane 8k
    const unsigned mask = 0xFFFFFFFFu;
    res += __shfl_down_sync(mask, res, 4);
    res += __shfl_down_sync(mask, res, 2);
    res += __shfl_down_sync(mask, res, 1);

    if ((threadIdx.x & 7) == 0) {
        out[(blockIdx.x * 256 + threadIdx.x) >> 3] = w * res;
    }
}

extern "C" void kernel_launch(void* const* d_in, const int* in_sizes, int n_in,
                              void* d_out, int out_size)
{
    const float* link_pos = (const float*)d_in[0];  // [1024,32,8,3]
    const float* link_rot = (const float*)d_in[1];  // [1024,32,8,3,3]
    const float* sph_ctr  = (const float*)d_in[2];  // [8,8,3]
    const float* sph_rad  = (const float*)d_in[3];  // [8,8]
    const float* sdf      = (const float*)d_in[4];  // [256,256,256]
    const float* weight   = (const float*)d_in[5];  // scalar
    float* out = (float*)d_out;                     // [1024,32]

    const int total = NB * NH * NL;                 // 262144 threads
    voxel_collision_kernel<<<total / 256, 256>>>(link_pos, link_rot, sph_ctr,
                                                 sph_rad, sdf, weight, out);
}

// round 6
// speedup vs baseline: 1.5690x; 1.5690x over previous
#include <cuda_runtime.h>
#include <cuda_bf16.h>
#include <cstdint>

// Problem constants
#define GRID_N   256
#define NB       1024
#define NH       32
#define NL       8
#define NS       8
#define BOUNDS_LO (-1.28f)
#define GRID_RES  (0.01f)
#define DIST_THR  (-0.01f)

// Fractional evict-last L2 policy (scalar-load compatible cache_hint form).
__device__ __forceinline__ uint64_t make_evict_last_policy() {
    uint64_t pol;
    asm("createpolicy.fractional.L2::evict_last.b64 %0, 1.0;" : "=l"(pol));
    return pol;
}

// SDF gather with L2 evict-last hint: keep the voxel grid resident in L2.
__device__ __forceinline__ float ldg_sdf(const float* p, uint64_t pol) {
    float v;
    asm volatile("ld.global.nc.L2::cache_hint.f32 %0, [%1], %2;"
                 : "=f"(v) : "l"(p), "l"(pol));
    return v;
}

// 2 threads per (b,h,l): each handles 4 spheres (MLP=4), 524288 threads total.
// Pose data staged through shared via coalesced, streaming (evict-first) float4
// loads so the read-once pose stream doesn't evict the SDF grid from L2.
__global__ __launch_bounds__(256, 8)
void voxel_collision_kernel(const float* __restrict__ link_pos,   // [B,H,L,3]
                            const float* __restrict__ link_rot,   // [B,H,L,3,3]
                            const float* __restrict__ sph_ctr,    // [L,S,3]
                            const float* __restrict__ sph_rad,    // [L,S]
                            const float* __restrict__ sdf,        // [256^3]
                            const float* __restrict__ weight,     // scalar
                            float* __restrict__ out)              // [B,H]
{
    // Block covers 128 (b,h,l) units.
    __shared__ float s_rot[128 * 9];       // 1152 floats = 4608 B
    __shared__ float s_pos[128 * 3];       // 384 floats
    __shared__ float s_ctr[NL * NS * 3];   // 192 floats
    __shared__ float s_rad[NL * NS];       // 64 floats

    // Coalesced, streaming staging of this block's pose data.
    {
        const float4* g4 = (const float4*)(link_rot + (size_t)blockIdx.x * 1152);
        float4* s4 = (float4*)s_rot;
        #pragma unroll
        for (int i = threadIdx.x; i < 288; i += 256) s4[i] = __ldcs(&g4[i]);

        const float4* p4 = (const float4*)(link_pos + (size_t)blockIdx.x * 384);
        float4* sp4 = (float4*)s_pos;
        if (threadIdx.x < 96) sp4[threadIdx.x] = __ldcs(&p4[threadIdx.x]);

        if (threadIdx.x < NL * NS * 3) s_ctr[threadIdx.x] = sph_ctr[threadIdx.x];
        if (threadIdx.x < NL * NS)     s_rad[threadIdx.x] = sph_rad[threadIdx.x];
    }
    __syncthreads();

    const int u  = threadIdx.x >> 1;         // local (b,h,l) unit 0..127
    const int l  = u & (NL - 1);             // link id (block is 8-aligned)
    const int sb = (threadIdx.x & 1) * 4;    // sphere base: 0 or 4

    const float r00 = s_rot[u * 9 + 0], r01 = s_rot[u * 9 + 1], r02 = s_rot[u * 9 + 2];
    const float r10 = s_rot[u * 9 + 3], r11 = s_rot[u * 9 + 4], r12 = s_rot[u * 9 + 5];
    const float r20 = s_rot[u * 9 + 6], r21 = s_rot[u * 9 + 7], r22 = s_rot[u * 9 + 8];
    const float px = s_pos[u * 3 + 0], py = s_pos[u * 3 + 1], pz = s_pos[u * 3 + 2];

    const uint64_t pol = make_evict_last_policy();

    // 4 gather addresses computed back-to-back, then 4 independent loads.
    float sval[4];
    #pragma unroll
    for (int s = 0; s < 4; s++) {
        const float* c = &s_ctr[(l * NS + sb + s) * 3];
        const float cx = c[0], cy = c[1], cz = c[2];
        // mul-then-add, round-to-nearest, no FMA contraction (bit-identical to
        // the passing rounds' numerics; rel_err 1.95e-4).
        float x = __fadd_rn(__fadd_rn(__fadd_rn(__fmul_rn(r00, cx), __fmul_rn(r01, cy)), __fmul_rn(r02, cz)), px);
        float y = __fadd_rn(__fadd_rn(__fadd_rn(__fmul_rn(r10, cx), __fmul_rn(r11, cy)), __fmul_rn(r12, cz)), py);
        float z = __fadd_rn(__fadd_rn(__fadd_rn(__fmul_rn(r20, cx), __fmul_rn(r21, cy)), __fmul_rn(r22, cz)), pz);

        int ix = (int)floorf(__fdiv_rn(__fsub_rn(x, BOUNDS_LO), GRID_RES));
        int iy = (int)floorf(__fdiv_rn(__fsub_rn(y, BOUNDS_LO), GRID_RES));
        int iz = (int)floorf(__fdiv_rn(__fsub_rn(z, BOUNDS_LO), GRID_RES));
        ix = min(max(ix, 0), GRID_N - 1);
        iy = min(max(iy, 0), GRID_N - 1);
        iz = min(max(iz, 0), GRID_N - 1);
        sval[s] = ldg_sdf(&sdf[((ix * GRID_N) + iy) * GRID_N + iz], pol);
    }

    const float w = __ldg(weight);           // off the critical path

    // worst penetration over this thread's 4 spheres
    float m = -1e30f;
    #pragma unroll
    for (int s = 0; s < 4; s++)
        m = fmaxf(m, s_rad[l * NS + sb + s] - sval[s]);

    // combine the two half-threads of this link (adjacent lanes)
    const unsigned mask = 0xFFFFFFFFu;
    m = fmaxf(m, __shfl_xor_sync(mask, m, 1));

    // threshold / clamp / normalize:  clip(m - 0.01, 0, 0.5) / 0.25
    float res = m + DIST_THR;
    res = fminf(fmaxf(res, 0.0f), 0.5f) * 4.0f;

    // sum 8 links of one (b,h): lanes [16k .. 16k+15], one value per lane pair.
    res += __shfl_down_sync(mask, res, 2);
    res += __shfl_down_sync(mask, res, 4);
    res += __shfl_down_sync(mask, res, 8);

    if ((threadIdx.x & 15) == 0) {
        out[(blockIdx.x * 256 + threadIdx.x) >> 4] = w * res;
    }
}

extern "C" void kernel_launch(void* const* d_in, const int* in_sizes, int n_in,
                              void* d_out, int out_size)
{
    const float* link_pos = (const float*)d_in[0];  // [1024,32,8,3]
    const float* link_rot = (const float*)d_in[1];  // [1024,32,8,3,3]
    const float* sph_ctr  = (const float*)d_in[2];  // [8,8,3]
    const float* sph_rad  = (const float*)d_in[3];  // [8,8]
    const float* sdf      = (const float*)d_in[4];  // [256,256,256]
    const float* weight   = (const float*)d_in[5];  // scalar
    float* out = (float*)d_out;                     // [1024,32]

    const int total = NB * NH * NL * 2;             // 524288 threads
    voxel_collision_kernel<<<total / 256, 256>>>(link_pos, link_rot, sph_ctr,
                                                 sph_rad, sdf, weight, out);
}